// round 4
// baseline (speedup 1.0000x reference)
#include <cuda_runtime.h>

#define NN 50000
#define EE 500000
#define FF 64
#define HH 4

// ---------------- scratch (device globals; no allocation allowed) ----------------
__device__ __align__(16) float g_proj[NN * HH * FF];   // [n][h][f]  51.2 MB
__device__ __align__(16) float g_sc[NN * 8];           // node scores [rad h0..3, tan h0..3]
__device__ __align__(16) float g_ssum[NN * 8];         // softmax denominators
__device__ __align__(16) float g_ex[(size_t)EE * 8];   // per-edge exp(logit)
__device__ __align__(16) float g_acc[NN * FF];         // scattered messages (already /4 head-mean)

__device__ __forceinline__ void red_add_v4(float* p, float4 v) {
    asm volatile("red.global.add.v4.f32 [%0], {%1,%2,%3,%4};"
                 :: "l"(p), "f"(v.x), "f"(v.y), "f"(v.z), "f"(v.w) : "memory");
}

// ---------------- init: zero accumulators ----------------
__global__ void init_kernel() {
    int i = blockIdx.x * blockDim.x + threadIdx.x;
    int stride = gridDim.x * blockDim.x;
    for (int j = i; j < NN * FF; j += stride) g_acc[j] = 0.f;
    for (int j = i; j < NN * 8; j += stride) g_ssum[j] = 0.f;
}

// ---------------- per-node projection + node scores ----------------
// proj[n,h,g] = sum_f x[n,f] * w_proj[h,f,g]
// sc[n,i]    = sum_f x[n,f] * wrt[i,f],  wrt[i,f] = sum_g w_proj[h,f,g]*score[h,g]
#define PT 32  // nodes per tile
__global__ void proj_kernel(const float* __restrict__ x,
                            const float* __restrict__ w_proj,
                            const float* __restrict__ rs,
                            const float* __restrict__ ts) {
    extern __shared__ float sh[];
    float* wsh = sh;                // [64][256]  wsh[f*256 + h*64 + g]
    float* xs  = sh + 64 * 256;     // [PT][65]   padded
    float* wrt = xs + PT * 65;      // [8][65]    padded

    int tid = threadIdx.x;

    // load weights, transposed to [f][h*64+g]
    for (int idx = tid; idx < 64 * 256; idx += 256) {
        int f = idx >> 8, c = idx & 255;
        int h = c >> 6, g = c & 63;
        wsh[idx] = w_proj[h * 4096 + f * 64 + g];
    }
    __syncthreads();

    // wrt[i][f]
    for (int e = tid; e < 8 * 64; e += 256) {
        int i = e >> 6, f = e & 63;
        int h = i & 3;
        const float* sc = (i < 4) ? rs : ts;
        float s = 0.f;
        #pragma unroll 8
        for (int g = 0; g < 64; g++) s += wsh[f * 256 + h * 64 + g] * sc[h * 64 + g];
        wrt[i * 65 + f] = s;
    }

    int lane = tid & 63, grp = tid >> 6;
    int ntiles = (NN + PT - 1) / PT;

    for (int tile = blockIdx.x; tile < ntiles; tile += gridDim.x) {
        int n0 = tile * PT;
        __syncthreads();  // also orders wrt writes before first phase2 read
        for (int idx = tid; idx < PT * 64; idx += 256) {
            int nd = idx >> 6, f = idx & 63;
            int n = n0 + nd;
            xs[nd * 65 + f] = (n < NN) ? x[n * 64 + f] : 0.f;
        }
        __syncthreads();

        float acc[4][8];
        #pragma unroll
        for (int h = 0; h < 4; h++)
            #pragma unroll
            for (int j = 0; j < 8; j++) acc[h][j] = 0.f;

        #pragma unroll 4
        for (int f = 0; f < 64; f++) {
            float w0 = wsh[f * 256 + lane];
            float w1 = wsh[f * 256 + 64 + lane];
            float w2 = wsh[f * 256 + 128 + lane];
            float w3 = wsh[f * 256 + 192 + lane];
            #pragma unroll
            for (int j = 0; j < 8; j++) {
                float xv = xs[(grp * 8 + j) * 65 + f];
                acc[0][j] += w0 * xv;
                acc[1][j] += w1 * xv;
                acc[2][j] += w2 * xv;
                acc[3][j] += w3 * xv;
            }
        }

        #pragma unroll
        for (int j = 0; j < 8; j++) {
            int n = n0 + grp * 8 + j;
            if (n < NN) {
                g_proj[n * 256 + lane]       = acc[0][j];
                g_proj[n * 256 + 64 + lane]  = acc[1][j];
                g_proj[n * 256 + 128 + lane] = acc[2][j];
                g_proj[n * 256 + 192 + lane] = acc[3][j];
            }
        }

        // node scores: thread -> (node tid/8, score-index tid%8)
        int nd2 = tid >> 3, i2 = tid & 7;
        int n2 = n0 + nd2;
        if (n2 < NN) {
            float s = 0.f;
            #pragma unroll 8
            for (int f = 0; f < 64; f++) s += xs[nd2 * 65 + f] * wrt[i2 * 65 + f];
            g_sc[n2 * 8 + i2] = s;
        }
    }
}

// ---------------- edge pass 1: exp(logits), accumulate softmax sums ----------------
__global__ void edge_pass1(const int* __restrict__ ei,
                           const float* __restrict__ elen,
                           const float* __restrict__ rds) {
    int i = blockIdx.x * blockDim.x + threadIdx.x;
    if (i >= EE) return;
    float scale = rds[0];
    int s = ei[i], r = ei[EE + i];
    const float4* scp = (const float4*)g_sc;
    float4 a0 = scp[s * 2], a1 = scp[s * 2 + 1];
    float4 b0 = scp[r * 2], b1 = scp[r * 2 + 1];
    float d = scale * elen[i];
    float4 er, et;
    er.x = __expf(a0.x - b0.x - d); er.y = __expf(a0.y - b0.y - d);
    er.z = __expf(a0.z - b0.z - d); er.w = __expf(a0.w - b0.w - d);
    et.x = __expf(a1.x - b1.x);     et.y = __expf(a1.y - b1.y);
    et.z = __expf(a1.z - b1.z);     et.w = __expf(a1.w - b1.w);
    float4* exp_ptr = (float4*)(g_ex + (size_t)i * 8);
    exp_ptr[0] = er;
    exp_ptr[1] = et;
    red_add_v4(g_ssum + r * 8, er);
    red_add_v4(g_ssum + r * 8 + 4, et);
}

// ---------------- edge pass 2: alpha-weighted scatter of sender proj ----------------
// half-warp (16 lanes) per edge; lane sub handles float4 chunk sub of the 64-f row
__global__ void edge_pass2(const int* __restrict__ ei) {
    int lane = threadIdx.x & 31;
    int gwarp = (blockIdx.x * blockDim.x + threadIdx.x) >> 5;
    int half = lane >> 4, sub = lane & 15;
    int e = gwarp * 2 + half;
    if (e >= EE) return;
    int s = ei[e], r = ei[EE + e];
    float a = 0.f;
    if (sub < 8) a = g_ex[(size_t)e * 8 + sub] / g_ssum[r * 8 + sub];
    // combined per-head weight = alpha_rad[h] + alpha_tan[h]
    float w0 = __shfl_sync(0xffffffffu, a, 0, 16) + __shfl_sync(0xffffffffu, a, 4, 16);
    float w1 = __shfl_sync(0xffffffffu, a, 1, 16) + __shfl_sync(0xffffffffu, a, 5, 16);
    float w2 = __shfl_sync(0xffffffffu, a, 2, 16) + __shfl_sync(0xffffffffu, a, 6, 16);
    float w3 = __shfl_sync(0xffffffffu, a, 3, 16) + __shfl_sync(0xffffffffu, a, 7, 16);
    const float4* p = (const float4*)(g_proj + (size_t)s * 256);
    float4 p0 = p[sub], p1 = p[16 + sub], p2 = p[32 + sub], p3 = p[48 + sub];
    float4 v;
    // 0.25 = mean over 4 heads, applied ONCE here (epilogue must NOT rescale g_acc)
    v.x = 0.25f * (w0 * p0.x + w1 * p1.x + w2 * p2.x + w3 * p3.x);
    v.y = 0.25f * (w0 * p0.y + w1 * p1.y + w2 * p2.y + w3 * p3.y);
    v.z = 0.25f * (w0 * p0.z + w1 * p1.z + w2 * p2.z + w3 * p3.z);
    v.w = 0.25f * (w0 * p0.w + w1 * p1.w + w2 * p2.w + w3 * p3.w);
    red_add_v4(g_acc + r * 64 + sub * 4, v);
}

// ---------------- epilogue: msg, residual + out-GEMM ----------------
// warp handles 4 nodes; out[n,g] = x[n,g] + sum_f msg[n,f]*w_out[f,g]
// msg[n,f] = g_acc[n,f] - 0.5*flag*sum_h proj[n,h,f]
//   (g_acc already head-averaged; receiver term = 2 softmaxes * (1/4 mean) = 0.5)
__global__ void epilogue_kernel(const float* __restrict__ x,
                                const float* __restrict__ w_out,
                                float* __restrict__ out) {
    __shared__ float wsh[64 * 64];
    __shared__ float msh[8][4][64];
    int tid = threadIdx.x, lane = tid & 31, wid = tid >> 5;
    for (int idx = tid; idx < 4096; idx += 256) wsh[idx] = w_out[idx];
    __syncthreads();

    int base = (blockIdx.x * 8 + wid) * 4;
    if (base >= NN) return;

    #pragma unroll
    for (int j = 0; j < 4; j++) {
        int n = base + j;
        if (n >= NN) { msh[wid][j][lane] = 0.f; msh[wid][j][lane + 32] = 0.f; continue; }
        float ne = (g_ssum[n * 8] > 0.f) ? 0.5f : 0.f;
        const float* pr = g_proj + (size_t)n * 256;
        #pragma unroll
        for (int k = 0; k < 2; k++) {
            int f = lane + k * 32;
            float ps = pr[f] + pr[64 + f] + pr[128 + f] + pr[192 + f];
            msh[wid][j][f] = g_acc[n * 64 + f] - ne * ps;
        }
    }
    __syncwarp();

    float a0[4], a1[4];
    #pragma unroll
    for (int j = 0; j < 4; j++) {
        int n = base + j;
        if (n < NN) { a0[j] = x[n * 64 + lane]; a1[j] = x[n * 64 + lane + 32]; }
        else        { a0[j] = 0.f; a1[j] = 0.f; }
    }
    #pragma unroll 4
    for (int f = 0; f < 64; f++) {
        float w0 = wsh[f * 64 + lane], w1 = wsh[f * 64 + lane + 32];
        #pragma unroll
        for (int j = 0; j < 4; j++) {
            float mf = msh[wid][j][f];
            a0[j] += mf * w0;
            a1[j] += mf * w1;
        }
    }
    #pragma unroll
    for (int j = 0; j < 4; j++) {
        int n = base + j;
        if (n < NN) {
            out[n * 64 + lane]      = a0[j];
            out[n * 64 + lane + 32] = a1[j];
        }
    }
}

// ---------------- launch ----------------
extern "C" void kernel_launch(void* const* d_in, const int* in_sizes, int n_in,
                              void* d_out, int out_size) {
    const float* x      = (const float*)d_in[0];
    const int*   ei     = (const int*)d_in[1];
    // d_in[2] = edge_vec (unused by reference)
    const float* elen   = (const float*)d_in[3];
    const float* w_proj = (const float*)d_in[4];
    const float* rs     = (const float*)d_in[5];
    const float* ts     = (const float*)d_in[6];
    const float* rds    = (const float*)d_in[7];
    const float* w_out  = (const float*)d_in[8];
    float* out = (float*)d_out;

    const int shmem = (64 * 256 + PT * 65 + 8 * 65) * (int)sizeof(float);  // 75,936 B
    cudaFuncSetAttribute(proj_kernel, cudaFuncAttributeMaxDynamicSharedMemorySize, shmem);

    init_kernel<<<512, 256>>>();
    proj_kernel<<<296, 256, shmem>>>(x, w_proj, rs, ts);
    edge_pass1<<<(EE + 255) / 256, 256>>>(ei, elen, rds);
    // half-warp per edge: EE/2 warps total
    edge_pass2<<<((EE / 2) * 32 + 255) / 256, 256>>>(ei);
    epilogue_kernel<<<(NN + 31) / 32, 256>>>(x, w_out, out);
}

// round 5
// speedup vs baseline: 1.1590x; 1.1590x over previous
#include <cuda_runtime.h>
#include <cuda_fp16.h>

#define NN 50000
#define EE 500000
#define FF 64
#define HH 4

// ---------------- scratch (device globals; no allocation allowed) ----------------
__device__ __align__(16) __half2 g_projh[(size_t)NN * 128]; // [n][h][f] fp16, 25.6 MB
__device__ __align__(16) float2  g_psum2[(size_t)NN * 32];  // [n][f] fp32 sum over heads, 12.8 MB
__device__ __align__(16) float g_sc[NN * 8];                // node scores [rad h0..3, tan h0..3]
__device__ __align__(16) float g_ssum[NN * 8];              // softmax denominators
__device__ __align__(16) float g_ex[(size_t)EE * 8];        // per-edge exp(logit)
__device__ __align__(16) float g_acc[NN * FF];              // scattered messages (already /4 head-mean)

__device__ __forceinline__ void red_add_v4(float* p, float4 v) {
    asm volatile("red.global.add.v4.f32 [%0], {%1,%2,%3,%4};"
                 :: "l"(p), "f"(v.x), "f"(v.y), "f"(v.z), "f"(v.w) : "memory");
}

// packed fp32 FMA: d = a*b + c  (2 lanes per instruction, FFMA2)
__device__ __forceinline__ float2 fma2(float2 a, float2 b, float2 c) {
    float2 d;
    asm("fma.rn.f32x2 %0, %1, %2, %3;"
        : "=l"(reinterpret_cast<unsigned long long&>(d))
        : "l"(reinterpret_cast<unsigned long long&>(a)),
          "l"(reinterpret_cast<unsigned long long&>(b)),
          "l"(reinterpret_cast<unsigned long long&>(c)));
    return d;
}

// ---------------- init: zero accumulators ----------------
__global__ void init_kernel() {
    int i = blockIdx.x * blockDim.x + threadIdx.x;
    int stride = gridDim.x * blockDim.x;
    for (int j = i; j < NN * FF; j += stride) g_acc[j] = 0.f;
    for (int j = i; j < NN * 8; j += stride) g_ssum[j] = 0.f;
}

// ---------------- per-node projection (fp16 out + fp32 head-sum) + node scores ----------
// proj[n,h,g] = sum_f x[n,f] * w_proj[h,f,g]     -> g_projh (fp16), g_psum2 (fp32 sum_h)
// sc[n,i]     = sum_f x[n,f] * wrt[i,f],  wrt[i,f] = sum_g w_proj[h,f,g]*score[h,g]
#define PT 32  // nodes per tile
__global__ void proj_kernel(const float* __restrict__ x,
                            const float* __restrict__ w_proj,
                            const float* __restrict__ rs,
                            const float* __restrict__ ts) {
    extern __shared__ float sh[];
    float2* wsh2 = (float2*)sh;          // [64][128] pairs: wsh2[f*128 + h*32 + gp] = w[h,f,2gp..2gp+1]
    float*  xs   = sh + 64 * 256;        // [PT][65] padded
    float*  wrt  = xs + PT * 65;         // [8][65]  padded

    int tid = threadIdx.x;

    // load weights as float2 pairs, transposed to [f][h*32+gp]
    for (int idx = tid; idx < 64 * 128; idx += 256) {
        int f = idx >> 7, p = idx & 127;
        int h = p >> 5, gp = p & 31;
        wsh2[idx] = ((const float2*)w_proj)[h * 2048 + f * 32 + gp];
    }
    __syncthreads();

    // wrt[i][f]
    for (int e = tid; e < 8 * 64; e += 256) {
        int i = e >> 6, f = e & 63;
        int h = i & 3;
        const float* sc = (i < 4) ? rs : ts;
        float s = 0.f;
        #pragma unroll 8
        for (int gp = 0; gp < 32; gp++) {
            float2 w = wsh2[f * 128 + h * 32 + gp];
            s += w.x * sc[h * 64 + 2 * gp] + w.y * sc[h * 64 + 2 * gp + 1];
        }
        wrt[i * 65 + f] = s;
    }

    int pg = tid & 31;       // g-pair column (covers g = 2pg, 2pg+1 of every head)
    int ng = tid >> 5;       // node group (4 nodes each)
    int ntiles = (NN + PT - 1) / PT;

    for (int tile = blockIdx.x; tile < ntiles; tile += gridDim.x) {
        int n0 = tile * PT;
        __syncthreads();  // orders wrt/xs across tiles
        for (int idx = tid; idx < PT * 64; idx += 256) {
            int nd = idx >> 6, f = idx & 63;
            int n = n0 + nd;
            xs[nd * 65 + f] = (n < NN) ? x[n * 64 + f] : 0.f;
        }
        __syncthreads();

        float2 acc[4][4];  // [node j][head h] — pair (2pg,2pg+1)
        #pragma unroll
        for (int j = 0; j < 4; j++)
            #pragma unroll
            for (int h = 0; h < 4; h++) acc[j][h] = make_float2(0.f, 0.f);

        #pragma unroll 4
        for (int f = 0; f < 64; f++) {
            float2 w0 = wsh2[f * 128 + pg];
            float2 w1 = wsh2[f * 128 + 32 + pg];
            float2 w2 = wsh2[f * 128 + 64 + pg];
            float2 w3 = wsh2[f * 128 + 96 + pg];
            #pragma unroll
            for (int j = 0; j < 4; j++) {
                float xv = xs[(ng * 4 + j) * 65 + f];
                float2 xx = make_float2(xv, xv);
                acc[j][0] = fma2(w0, xx, acc[j][0]);
                acc[j][1] = fma2(w1, xx, acc[j][1]);
                acc[j][2] = fma2(w2, xx, acc[j][2]);
                acc[j][3] = fma2(w3, xx, acc[j][3]);
            }
        }

        #pragma unroll
        for (int j = 0; j < 4; j++) {
            int n = n0 + ng * 4 + j;
            if (n < NN) {
                __half2* op = g_projh + (size_t)n * 128;   // [h*32 + pg]
                op[pg]      = __float22half2_rn(acc[j][0]);
                op[32 + pg] = __float22half2_rn(acc[j][1]);
                op[64 + pg] = __float22half2_rn(acc[j][2]);
                op[96 + pg] = __float22half2_rn(acc[j][3]);
                float2 ps;
                ps.x = acc[j][0].x + acc[j][1].x + acc[j][2].x + acc[j][3].x;
                ps.y = acc[j][0].y + acc[j][1].y + acc[j][2].y + acc[j][3].y;
                g_psum2[(size_t)n * 32 + pg] = ps;
            }
        }

        // node scores: thread -> (node tid/8, score-index tid%8)
        int nd2 = tid >> 3, i2 = tid & 7;
        int n2 = n0 + nd2;
        if (n2 < NN) {
            float s = 0.f;
            #pragma unroll 8
            for (int f = 0; f < 64; f++) s += xs[nd2 * 65 + f] * wrt[i2 * 65 + f];
            g_sc[n2 * 8 + i2] = s;
        }
    }
}

// ---------------- edge pass 1: exp(logits), accumulate softmax sums ----------------
__global__ void edge_pass1(const int* __restrict__ ei,
                           const float* __restrict__ elen,
                           const float* __restrict__ rds) {
    int i = blockIdx.x * blockDim.x + threadIdx.x;
    if (i >= EE) return;
    float scale = rds[0];
    int s = ei[i], r = ei[EE + i];
    const float4* scp = (const float4*)g_sc;
    float4 a0 = scp[s * 2], a1 = scp[s * 2 + 1];
    float4 b0 = scp[r * 2], b1 = scp[r * 2 + 1];
    float d = scale * elen[i];
    float4 er, et;
    er.x = __expf(a0.x - b0.x - d); er.y = __expf(a0.y - b0.y - d);
    er.z = __expf(a0.z - b0.z - d); er.w = __expf(a0.w - b0.w - d);
    et.x = __expf(a1.x - b1.x);     et.y = __expf(a1.y - b1.y);
    et.z = __expf(a1.z - b1.z);     et.w = __expf(a1.w - b1.w);
    float4* exp_ptr = (float4*)(g_ex + (size_t)i * 8);
    exp_ptr[0] = er;
    exp_ptr[1] = et;
    red_add_v4(g_ssum + r * 8, er);
    red_add_v4(g_ssum + r * 8 + 4, et);
}

// ---------------- edge pass 2: alpha-weighted scatter of fp16 sender proj ------------
// half-warp (16 lanes) per edge; lane sub handles f-chunk [4sub, 4sub+3] of every head
__global__ void edge_pass2(const int* __restrict__ ei) {
    int lane = threadIdx.x & 31;
    int gwarp = (blockIdx.x * blockDim.x + threadIdx.x) >> 5;
    int half = lane >> 4, sub = lane & 15;
    int e = gwarp * 2 + half;
    if (e >= EE) return;
    int s = ei[e], r = ei[EE + e];
    float a = 0.f;
    if (sub < 8) a = g_ex[(size_t)e * 8 + sub] / g_ssum[r * 8 + sub];
    // combined per-head weight = alpha_rad[h] + alpha_tan[h]
    float w0 = __shfl_sync(0xffffffffu, a, 0, 16) + __shfl_sync(0xffffffffu, a, 4, 16);
    float w1 = __shfl_sync(0xffffffffu, a, 1, 16) + __shfl_sync(0xffffffffu, a, 5, 16);
    float w2 = __shfl_sync(0xffffffffu, a, 2, 16) + __shfl_sync(0xffffffffu, a, 6, 16);
    float w3 = __shfl_sync(0xffffffffu, a, 3, 16) + __shfl_sync(0xffffffffu, a, 7, 16);

    // fp16 row: 256 halves = 64 uint2; head h occupies uint2 [h*16, h*16+15]
    const uint2* ph = (const uint2*)g_projh + (size_t)s * 64;
    uint2 q0 = ph[sub], q1 = ph[16 + sub], q2 = ph[32 + sub], q3 = ph[48 + sub];

    float2 lo = make_float2(0.f, 0.f), hi = make_float2(0.f, 0.f);
    {
        float2 ca = __half22float2(*(const __half2*)&q0.x);
        float2 cb = __half22float2(*(const __half2*)&q0.y);
        lo.x += w0 * ca.x; lo.y += w0 * ca.y; hi.x += w0 * cb.x; hi.y += w0 * cb.y;
    }
    {
        float2 ca = __half22float2(*(const __half2*)&q1.x);
        float2 cb = __half22float2(*(const __half2*)&q1.y);
        lo.x += w1 * ca.x; lo.y += w1 * ca.y; hi.x += w1 * cb.x; hi.y += w1 * cb.y;
    }
    {
        float2 ca = __half22float2(*(const __half2*)&q2.x);
        float2 cb = __half22float2(*(const __half2*)&q2.y);
        lo.x += w2 * ca.x; lo.y += w2 * ca.y; hi.x += w2 * cb.x; hi.y += w2 * cb.y;
    }
    {
        float2 ca = __half22float2(*(const __half2*)&q3.x);
        float2 cb = __half22float2(*(const __half2*)&q3.y);
        lo.x += w3 * ca.x; lo.y += w3 * ca.y; hi.x += w3 * cb.x; hi.y += w3 * cb.y;
    }
    float4 v;  // 0.25 = head mean, applied once here
    v.x = 0.25f * lo.x; v.y = 0.25f * lo.y; v.z = 0.25f * hi.x; v.w = 0.25f * hi.y;
    red_add_v4(g_acc + r * 64 + sub * 4, v);
}

// ---------------- epilogue: msg, residual + out-GEMM (packed f32x2) ----------------
// warp handles 4 nodes; lane handles output-column pair (2lane, 2lane+1)
// msg[n,f] = g_acc[n,f] - 0.5*flag*psum[n,f]
__global__ void epilogue_kernel(const float* __restrict__ x,
                                const float* __restrict__ w_out,
                                float* __restrict__ out) {
    __shared__ float2 wsh2[64 * 32];     // [f][gp]
    __shared__ float msh[8][4][64];
    int tid = threadIdx.x, lane = tid & 31, wid = tid >> 5;
    for (int idx = tid; idx < 2048; idx += 256) wsh2[idx] = ((const float2*)w_out)[idx];
    __syncthreads();

    int base = (blockIdx.x * 8 + wid) * 4;
    if (base >= NN) return;

    const float* psum = (const float*)g_psum2;
    #pragma unroll
    for (int j = 0; j < 4; j++) {
        int n = base + j;
        if (n >= NN) { msh[wid][j][lane] = 0.f; msh[wid][j][lane + 32] = 0.f; continue; }
        float ne = (g_ssum[n * 8] > 0.f) ? 0.5f : 0.f;
        #pragma unroll
        for (int k = 0; k < 2; k++) {
            int f = lane + k * 32;
            msh[wid][j][f] = g_acc[n * 64 + f] - ne * psum[(size_t)n * 64 + f];
        }
    }
    __syncwarp();

    float2 a2[4];
    #pragma unroll
    for (int j = 0; j < 4; j++) {
        int n = base + j;
        a2[j] = (n < NN) ? ((const float2*)x)[n * 32 + lane] : make_float2(0.f, 0.f);
    }
    #pragma unroll 4
    for (int f = 0; f < 64; f++) {
        float2 w = wsh2[f * 32 + lane];
        #pragma unroll
        for (int j = 0; j < 4; j++) {
            float m = msh[wid][j][f];
            a2[j] = fma2(w, make_float2(m, m), a2[j]);
        }
    }
    #pragma unroll
    for (int j = 0; j < 4; j++) {
        int n = base + j;
        if (n < NN) ((float2*)out)[n * 32 + lane] = a2[j];
    }
}

// ---------------- launch ----------------
extern "C" void kernel_launch(void* const* d_in, const int* in_sizes, int n_in,
                              void* d_out, int out_size) {
    const float* x      = (const float*)d_in[0];
    const int*   ei     = (const int*)d_in[1];
    // d_in[2] = edge_vec (unused by reference)
    const float* elen   = (const float*)d_in[3];
    const float* w_proj = (const float*)d_in[4];
    const float* rs     = (const float*)d_in[5];
    const float* ts     = (const float*)d_in[6];
    const float* rds    = (const float*)d_in[7];
    const float* w_out  = (const float*)d_in[8];
    float* out = (float*)d_out;

    const int shmem = (64 * 256 + PT * 65 + 8 * 65) * (int)sizeof(float);  // 75,936 B
    cudaFuncSetAttribute(proj_kernel, cudaFuncAttributeMaxDynamicSharedMemorySize, shmem);

    init_kernel<<<512, 256>>>();
    proj_kernel<<<296, 256, shmem>>>(x, w_proj, rs, ts);
    edge_pass1<<<(EE + 255) / 256, 256>>>(ei, elen, rds);
    // half-warp per edge: EE/2 warps total
    edge_pass2<<<((EE / 2) * 32 + 255) / 256, 256>>>(ei);
    epilogue_kernel<<<(NN + 31) / 32, 256>>>(x, w_out, out);
}